// round 2
// baseline (speedup 1.0000x reference)
#include <cuda_runtime.h>
#include <cuda_bf16.h>
#include <cstdint>

// ---------------------------------------------------------------------------
// Problem constants
// ---------------------------------------------------------------------------
#define NROWS   50000      // N_ART == N_COMM
#define F_IN    768
#define PROJ    1024
#define HID     256
#define OUTD    128
#define EMAX    500000

// ---------------------------------------------------------------------------
// Static device scratch (no allocations allowed)
// ---------------------------------------------------------------------------
__device__ float g_WA [F_IN * 512];        // [W1@Wl1 | W1@Wl2]   768x512
__device__ float g_WC [F_IN * 512];        // [W2@Wr1 | Wr3]      768x512
__device__ float g_bA [512];               // [b1@Wl1 | b1@Wl2]
__device__ float g_bC [512];               // [b2@Wr1 | 0]
__device__ float g_A12[(size_t)NROWS * 512];  // article contributions (A1|A2)
__device__ float g_CC [(size_t)NROWS * 512];  // community terms (C1|CR3)
__device__ float g_h1 [(size_t)NROWS * HID];
__device__ float g_h1r[(size_t)NROWS * HID];  // h1 @ Wr2
__device__ float g_h2 [(size_t)NROWS * HID];
__device__ float g_t  [(size_t)NROWS * HID];  // h2 @ Wl3
__device__ float g_h3 [(size_t)NROWS * HID];
__device__ int   g_cnt[NROWS];
__device__ int   g_rowstart[NROWS + 1];
__device__ int   g_cursor[NROWS];
__device__ int   g_csr[EMAX];

// ---------------------------------------------------------------------------
// SGEMM: C[M,N] = A[M,K] @ B[K,N] (+bias per column). Row-major, strided.
// Requires: N % 128 == 0, K % 16 == 0, lda/ldb/ldc multiples of 4.
// M arbitrary (guarded).
// ---------------------------------------------------------------------------
#define BM 128
#define BN 128
#define BK 16
#define TM 8
#define TN 8

__global__ __launch_bounds__(256)
void sgemm_kernel(int M, int N, int K,
                  const float* __restrict__ A, int lda,
                  const float* __restrict__ B, int ldb,
                  float* __restrict__ C, int ldc,
                  const float* __restrict__ bias)
{
    __shared__ float As[BK][BM];
    __shared__ float Bs[BK][BN];

    const int cRow = blockIdx.x;
    const int cCol = blockIdx.y;
    const int tid  = threadIdx.x;

    const int threadCol = tid % (BN / TN);   // 0..15
    const int threadRow = tid / (BN / TN);   // 0..15

    const int innerRowA = tid / (BK / 4);    // 0..63
    const int innerColA = tid % (BK / 4);    // 0..3
    const int innerRowB = tid / (BN / 4);    // 0..7
    const int innerColB = tid % (BN / 4);    // 0..31

    float acc[TM][TN];
#pragma unroll
    for (int i = 0; i < TM; i++)
#pragma unroll
        for (int j = 0; j < TN; j++) acc[i][j] = 0.0f;

    float regM[TM], regN[TN];

    const float* Abase = A + (size_t)cRow * BM * lda;
    const float* Bbase = B + (size_t)cCol * BN;

    for (int k0 = 0; k0 < K; k0 += BK) {
        // load A tile (128x16), transpose into As[k][m]
#pragma unroll
        for (int p = 0; p < 2; p++) {
            int r    = innerRowA + p * 64;
            int grow = cRow * BM + r;
            float4 v = make_float4(0.f, 0.f, 0.f, 0.f);
            if (grow < M)
                v = *(const float4*)(Abase + (size_t)r * lda + k0 + innerColA * 4);
            As[innerColA * 4 + 0][r] = v.x;
            As[innerColA * 4 + 1][r] = v.y;
            As[innerColA * 4 + 2][r] = v.z;
            As[innerColA * 4 + 3][r] = v.w;
        }
        // load B tile (16x128)
#pragma unroll
        for (int p = 0; p < 2; p++) {
            int r = innerRowB + p * 8;
            float4 v = *(const float4*)(Bbase + (size_t)(k0 + r) * ldb + innerColB * 4);
            *(float4*)&Bs[r][innerColB * 4] = v;
        }
        __syncthreads();

#pragma unroll
        for (int k = 0; k < BK; k++) {
#pragma unroll
            for (int i = 0; i < TM; i++) regM[i] = As[k][threadRow * TM + i];
#pragma unroll
            for (int j = 0; j < TN; j++) regN[j] = Bs[k][threadCol * TN + j];
#pragma unroll
            for (int i = 0; i < TM; i++)
#pragma unroll
                for (int j = 0; j < TN; j++)
                    acc[i][j] += regM[i] * regN[j];
        }
        __syncthreads();
    }

#pragma unroll
    for (int i = 0; i < TM; i++) {
        int grow = cRow * BM + threadRow * TM + i;
        if (grow >= M) continue;
#pragma unroll
        for (int j = 0; j < TN; j += 4) {
            int gcol = cCol * BN + threadCol * TN + j;
            float4 v;
            v.x = acc[i][j + 0]; v.y = acc[i][j + 1];
            v.z = acc[i][j + 2]; v.w = acc[i][j + 3];
            if (bias) {
                v.x += bias[gcol + 0]; v.y += bias[gcol + 1];
                v.z += bias[gcol + 2]; v.w += bias[gcol + 3];
            }
            *(float4*)(C + (size_t)grow * ldc + gcol) = v;
        }
    }
}

// ---------------------------------------------------------------------------
// out[col_off + c] = sum_k b[k] * W[k*ldw + c]   (vector-matrix, tiny)
// ---------------------------------------------------------------------------
__global__ void vecmat_kernel(const float* __restrict__ b,
                              const float* __restrict__ W,
                              int K, int ldw,
                              float* __restrict__ out, int n, int col_off)
{
    int c = blockIdx.x * blockDim.x + threadIdx.x;
    if (c >= n) return;
    float a = 0.f;
    for (int k = 0; k < K; k++) a += b[k] * W[(size_t)k * ldw + c];
    out[col_off + c] = a;
}

// copy src[rows x cols] (stride lds) into dst cols [dcol, dcol+cols) (stride ldd)
__global__ void copy_cols_kernel(const float* __restrict__ src, int lds,
                                 float* __restrict__ dst, int ldd,
                                 int rows, int cols, int dcol)
{
    int idx = blockIdx.x * blockDim.x + threadIdx.x;
    if (idx >= rows * cols) return;
    int r = idx / cols, c = idx % cols;
    dst[(size_t)r * ldd + dcol + c] = src[(size_t)r * lds + c];
}

// ---------------------------------------------------------------------------
// CSR build
// ---------------------------------------------------------------------------
__global__ void count_kernel(const int* __restrict__ dst, int E, int* __restrict__ cnt)
{
    int e = blockIdx.x * blockDim.x + threadIdx.x;
    if (e < E) atomicAdd(&cnt[dst[e]], 1);
}

// single-block exclusive scan over n ints (chunked, warp-shuffle based)
__global__ void scan_kernel(const int* __restrict__ cnt, int* __restrict__ rowstart, int n)
{
    __shared__ int warp_sums[32];
    __shared__ int s_carry;
    int tid = threadIdx.x, lane = tid & 31, wid = tid >> 5;
    if (tid == 0) s_carry = 0;
    __syncthreads();
    for (int base = 0; base < n; base += 1024) {
        int i = base + tid;
        int v = (i < n) ? cnt[i] : 0;
        int x = v;
#pragma unroll
        for (int off = 1; off < 32; off <<= 1) {
            int y = __shfl_up_sync(0xffffffffu, x, off);
            if (lane >= off) x += y;
        }
        if (lane == 31) warp_sums[wid] = x;
        __syncthreads();
        if (wid == 0) {
            int w = warp_sums[lane];
#pragma unroll
            for (int off = 1; off < 32; off <<= 1) {
                int y = __shfl_up_sync(0xffffffffu, w, off);
                if (lane >= off) w += y;
            }
            warp_sums[lane] = w;
        }
        __syncthreads();
        int warp_off = (wid > 0) ? warp_sums[wid - 1] : 0;
        int incl = x + warp_off;
        int carry = s_carry;
        if (i < n) rowstart[i] = carry + incl - v;
        __syncthreads();
        if (tid == 1023) s_carry = carry + incl;
        __syncthreads();
    }
    if (tid == 0) rowstart[n] = s_carry;
}

__global__ void copy_int_kernel(const int* __restrict__ s, int* __restrict__ d, int n)
{
    int i = blockIdx.x * blockDim.x + threadIdx.x;
    if (i < n) d[i] = s[i];
}

__global__ void fill_kernel(const int* __restrict__ src, const int* __restrict__ dst,
                            int E, int* __restrict__ cursor, int* __restrict__ csr)
{
    int e = blockIdx.x * blockDim.x + threadIdx.x;
    if (e < E) {
        int p = atomicAdd(&cursor[dst[e]], 1);
        csr[p] = src[e];
    }
}

// ---------------------------------------------------------------------------
// Fused mean-aggregate + bias + residual-linear term + ReLU.
// out[r,c] = relu( mean_{s in csr row r} S[s,c] + bias[c] + other[r,c] )
// One block per destination row, 256 threads = one column each.
// ---------------------------------------------------------------------------
__global__ __launch_bounds__(HID)
void aggregate_kernel(const int* __restrict__ rowstart, const int* __restrict__ csr,
                      const float* __restrict__ S, int ldS,
                      const float* __restrict__ other, int ldO,
                      const float* __restrict__ bias,
                      float* __restrict__ out, int ldOut)
{
    int r = blockIdx.x;
    int c = threadIdx.x;
    int s = rowstart[r], e = rowstart[r + 1];
    float accum = 0.f;
    for (int i = s; i < e; i++) {
        int srcRow = csr[i];
        accum += S[(size_t)srcRow * ldS + c];
    }
    float m = accum / fmaxf((float)(e - s), 1.0f);
    float v = m + bias[c] + other[(size_t)r * ldO + c];
    out[(size_t)r * ldOut + c] = fmaxf(v, 0.0f);
}

// ---------------------------------------------------------------------------
// Host-side launch helpers
// ---------------------------------------------------------------------------
static inline void launch_gemm(int M, int N, int K,
                               const float* A, int lda,
                               const float* B, int ldb,
                               float* C, int ldc, const float* bias)
{
    dim3 grid((M + BM - 1) / BM, N / BN);
    sgemm_kernel<<<grid, 256>>>(M, N, K, A, lda, B, ldb, C, ldc, bias);
}

static inline void process_edges(const int* e_base, int E,
                                 int* cnt, int* rowstart, int* cursor, int* csr,
                                 const float* S, int ldS,
                                 const float* other, int ldO,
                                 const float* bias, float* out)
{
    const int* src = e_base;
    const int* dst = e_base + E;
    cudaMemsetAsync(cnt, 0, NROWS * sizeof(int));
    count_kernel<<<(E + 255) / 256, 256>>>(dst, E, cnt);
    scan_kernel<<<1, 1024>>>(cnt, rowstart, NROWS);
    copy_int_kernel<<<(NROWS + 255) / 256, 256>>>(rowstart, cursor, NROWS);
    fill_kernel<<<(E + 255) / 256, 256>>>(src, dst, E, cursor, csr);
    aggregate_kernel<<<NROWS, HID>>>(rowstart, csr, S, ldS, other, ldO, bias, out, HID);
}

extern "C" void kernel_launch(void* const* d_in, const int* in_sizes, int n_in,
                              void* d_out, int out_size)
{
    const float* article_x   = (const float*)d_in[0];
    const float* community_x = (const float*)d_in[1];
    const int*   e_wb        = (const int*)d_in[2];
    const int*   e_mb        = (const int*)d_in[3];
    const int*   e_int       = (const int*)d_in[4];
    const float* W1  = (const float*)d_in[5];
    const float* b1  = (const float*)d_in[6];
    const float* W2  = (const float*)d_in[7];
    const float* b2  = (const float*)d_in[8];
    const float* Wl1 = (const float*)d_in[9];
    const float* bl1 = (const float*)d_in[10];
    const float* Wr1 = (const float*)d_in[11];
    const float* Wl2 = (const float*)d_in[12];
    const float* bl2 = (const float*)d_in[13];
    const float* Wr2 = (const float*)d_in[14];
    const float* Wl3 = (const float*)d_in[15];
    const float* bl3 = (const float*)d_in[16];
    const float* Wr3 = (const float*)d_in[17];
    const float* W3  = (const float*)d_in[18];
    const float* b3  = (const float*)d_in[19];

    const int E_wb  = in_sizes[2] / 2;
    const int E_mb  = in_sizes[3] / 2;
    const int E_int = in_sizes[4] / 2;

    float *WA, *WC, *bA, *bC, *A12, *CC, *h1, *h1r, *h2, *t, *h3;
    int   *cnt, *rowstart, *cursor, *csr;
    cudaGetSymbolAddress((void**)&WA,  g_WA);
    cudaGetSymbolAddress((void**)&WC,  g_WC);
    cudaGetSymbolAddress((void**)&bA,  g_bA);
    cudaGetSymbolAddress((void**)&bC,  g_bC);
    cudaGetSymbolAddress((void**)&A12, g_A12);
    cudaGetSymbolAddress((void**)&CC,  g_CC);
    cudaGetSymbolAddress((void**)&h1,  g_h1);
    cudaGetSymbolAddress((void**)&h1r, g_h1r);
    cudaGetSymbolAddress((void**)&h2,  g_h2);
    cudaGetSymbolAddress((void**)&t,   g_t);
    cudaGetSymbolAddress((void**)&h3,  g_h3);
    cudaGetSymbolAddress((void**)&cnt,      g_cnt);
    cudaGetSymbolAddress((void**)&rowstart, g_rowstart);
    cudaGetSymbolAddress((void**)&cursor,   g_cursor);
    cudaGetSymbolAddress((void**)&csr,      g_csr);

    // ---- Fold weights: WA = [W1@Wl1 | W1@Wl2], WC = [W2@Wr1 | Wr3] ----
    launch_gemm(F_IN, HID, PROJ, W1, PROJ, Wl1, HID, WA,        512, nullptr);
    launch_gemm(F_IN, HID, PROJ, W1, PROJ, Wl2, HID, WA + HID,  512, nullptr);
    launch_gemm(F_IN, HID, PROJ, W2, PROJ, Wr1, HID, WC,        512, nullptr);
    copy_cols_kernel<<<(F_IN * HID + 255) / 256, 256>>>(Wr3, HID, WC, 512, F_IN, HID, HID);

    // ---- Fold biases: bA = [b1@Wl1 | b1@Wl2], bC = [b2@Wr1 | 0] ----
    cudaMemsetAsync(bC, 0, 512 * sizeof(float));
    vecmat_kernel<<<1, 256>>>(b1, Wl1, PROJ, HID, bA, HID, 0);
    vecmat_kernel<<<1, 256>>>(b1, Wl2, PROJ, HID, bA, HID, HID);
    vecmat_kernel<<<1, 256>>>(b2, Wr1, PROJ, HID, bC, HID, 0);

    // ---- Big projections (the 1024-wide activations never materialize) ----
    // A12 = article_x @ WA + bA      [50000 x 512]
    launch_gemm(NROWS, 512, F_IN, article_x, F_IN, WA, 512, A12, 512, bA);
    // CC  = community_x @ WC + bC    [50000 x 512]
    launch_gemm(NROWS, 512, F_IN, community_x, F_IN, WC, 512, CC, 512, bC);

    // ---- conv1: h1 = relu(mean(A1[src]) + bl1 + C1) ----
    process_edges(e_wb, E_wb, cnt, rowstart, cursor, csr,
                  A12, 512, CC, 512, bl1, h1);

    // ---- conv2: h2 = relu(mean(A2[src]) + bl2 + h1@Wr2) ----
    launch_gemm(NROWS, HID, HID, h1, HID, Wr2, HID, h1r, HID, nullptr);
    process_edges(e_mb, E_mb, cnt, rowstart, cursor, csr,
                  A12 + HID, 512, h1r, HID, bl2, h2);

    // ---- conv3: h3 = relu(mean((h2@Wl3)[src]) + bl3 + community_x@Wr3) ----
    launch_gemm(NROWS, HID, HID, h2, HID, Wl3, HID, t, HID, nullptr);
    process_edges(e_int, E_int, cnt, rowstart, cursor, csr,
                  t, HID, CC + HID, 512, bl3, h3);

    // ---- out = h3 @ W3 + b3 ----
    launch_gemm(NROWS, OUTD, HID, h3, HID, W3, OUTD, (float*)d_out, OUTD, b3);
}

// round 5
// speedup vs baseline: 2.8534x; 2.8534x over previous
#include <cuda_runtime.h>
#include <cuda_fp16.h>
#include <cstdint>

// ---------------------------------------------------------------------------
// Problem constants
// ---------------------------------------------------------------------------
#define NROWS   50000
#define F_IN    768
#define PROJ    1024
#define HID     256
#define OUTD    128
#define EMAX    500000
#define NR ((size_t)NROWS)

// ---------------------------------------------------------------------------
// Arena of static device scratch (no runtime allocation allowed)
// ---------------------------------------------------------------------------
constexpr size_t OFF_AXH   = 0;                                   // half [NR x 768]
constexpr size_t OFF_CXH   = OFF_AXH + NR * F_IN * 2;             // half [NR x 768]
constexpr size_t OFF_A12H  = OFF_CXH + NR * F_IN * 2;             // half [NR x 512]
constexpr size_t OFF_CC    = OFF_A12H + NR * 512 * 2;             // fp32 [NR x 512]
constexpr size_t OFF_H1R   = OFF_CC + NR * 512 * 4;               // fp32 [NR x 256]
constexpr size_t OFF_TH    = OFF_H1R + NR * HID * 4;              // half [NR x 256]
constexpr size_t OFF_H1H   = OFF_TH + NR * HID * 2;               // half [NR x 256]
constexpr size_t OFF_H2H   = OFF_H1H + NR * HID * 2;
constexpr size_t OFF_H3H   = OFF_H2H + NR * HID * 2;
constexpr size_t OFF_W1H   = OFF_H3H + NR * HID * 2;              // half [768 x 1024]
constexpr size_t OFF_W2H   = OFF_W1H + (size_t)F_IN * PROJ * 2;
constexpr size_t OFF_WL1T  = OFF_W2H + (size_t)F_IN * PROJ * 2;   // half [256 x 1024]
constexpr size_t OFF_WL2T  = OFF_WL1T + (size_t)HID * PROJ * 2;
constexpr size_t OFF_WR1T  = OFF_WL2T + (size_t)HID * PROJ * 2;
constexpr size_t OFF_WAT   = OFF_WR1T + (size_t)HID * PROJ * 2;   // half [512 x 768]
constexpr size_t OFF_WCT   = OFF_WAT + (size_t)512 * F_IN * 2;    // half [512 x 768]
constexpr size_t OFF_WR2T  = OFF_WCT + (size_t)512 * F_IN * 2;    // half [256 x 256]
constexpr size_t OFF_WL3T  = OFF_WR2T + (size_t)HID * HID * 2;
constexpr size_t OFF_W3T   = OFF_WL3T + (size_t)HID * HID * 2;    // half [128 x 256]
constexpr size_t OFF_BA    = OFF_W3T + (size_t)OUTD * HID * 2;    // fp32 [512]
constexpr size_t OFF_BC    = OFF_BA + 512 * 4;                    // fp32 [512]
constexpr size_t OFF_CNT   = OFF_BC + 512 * 4;
constexpr size_t OFF_CURSOR= OFF_CNT + NR * 4;
constexpr size_t OFF_CSR   = OFF_CURSOR + NR * 4;
constexpr size_t OFF_ROWST = OFF_CSR + (size_t)EMAX * 4;
constexpr size_t ARENA_TOTAL = OFF_ROWST + (NR + 1) * 4 + 64;

__device__ unsigned char g_arena[ARENA_TOTAL];

__device__ __forceinline__ uint32_t smem_u32(const void* p) {
    uint32_t a;
    asm("{ .reg .u64 t; cvta.to.shared.u64 t, %1; cvt.u32.u64 %0, t; }" : "=r"(a) : "l"(p));
    return a;
}

// ---------------------------------------------------------------------------
// Tensor-core GEMM via mma.sync (base sm_103 ISA, no tcgen05 needed):
//   C[M,N] = A[M,K](fp16) @ B[N,K](fp16)^T  (+bias), fp32 accumulate.
// Tile 128x128x32, 8 warps (4Mx2N), warp tile 32x64, cp.async double buffer.
// smem rows padded to 40 halfs (80B stride -> conflict-free ldmatrix).
// Requires: N % 128 == 0, K % 32 == 0. M arbitrary.
// ---------------------------------------------------------------------------
#define GM 128
#define GN 128
#define GK 32
#define SROW 40

template<bool HALF_OUT>
__global__ void __launch_bounds__(256)
mma_gemm_kernel(int M, int N, int K,
                const __half* __restrict__ A,
                const __half* __restrict__ B,
                void* __restrict__ Cv, int ldc,
                const float* __restrict__ bias)
{
    __shared__ __half As[2][GM * SROW];
    __shared__ __half Bs[2][GN * SROW];

    const int tid = threadIdx.x;
    const int lane = tid & 31, wid = tid >> 5;
    const int warp_m = wid >> 1, warp_n = wid & 1;
    const int m0 = blockIdx.x * GM, n0 = blockIdx.y * GN;

    const uint32_t sA = smem_u32(As), sB = smem_u32(Bs);
    const int nk = K / GK;

    float acc[2][8][4];
#pragma unroll
    for (int i = 0; i < 2; i++)
#pragma unroll
        for (int j = 0; j < 8; j++)
#pragma unroll
            for (int q = 0; q < 4; q++) acc[i][j][q] = 0.f;

    auto issue = [&](int ch) {
        int buf = ch & 1;
        int k0 = ch * GK;
        uint32_t baseA = sA + buf * (GM * SROW * 2);
        uint32_t baseB = sB + buf * (GN * SROW * 2);
#pragma unroll
        for (int i = 0; i < 2; i++) {
            int idx = tid + i * 256;          // 0..511
            int row = idx >> 2;               // 0..127
            int c8  = (idx & 3) << 3;         // 0,8,16,24
            uint32_t soff = (uint32_t)(row * SROW + c8) * 2;
            int gr = m0 + row;
            const __half* ga = A + (size_t)(gr < M ? gr : 0) * K + k0 + c8;
            int sz = (gr < M) ? 16 : 0;
            asm volatile("cp.async.cg.shared.global [%0], [%1], 16, %2;"
                         :: "r"(baseA + soff), "l"(ga), "r"(sz));
            const __half* gb = B + (size_t)(n0 + row) * K + k0 + c8;
            asm volatile("cp.async.cg.shared.global [%0], [%1], 16;"
                         :: "r"(baseB + soff), "l"(gb));
        }
        asm volatile("cp.async.commit_group;");
    };

    issue(0);
    for (int ch = 0; ch < nk; ch++) {
        int buf = ch & 1;
        if (ch + 1 < nk) {
            issue(ch + 1);
            asm volatile("cp.async.wait_group 1;");
        } else {
            asm volatile("cp.async.wait_group 0;");
        }
        __syncthreads();

        uint32_t baseA = sA + buf * (GM * SROW * 2);
        uint32_t baseB = sB + buf * (GN * SROW * 2);
#pragma unroll
        for (int ks = 0; ks < 2; ks++) {
            int kk = ks * 16;
            uint32_t a[2][4];
#pragma unroll
            for (int wm = 0; wm < 2; wm++) {
                int row = warp_m * 32 + wm * 16 + (lane & 15);
                int col = kk + ((lane >> 4) << 3);
                uint32_t addr = baseA + (uint32_t)(row * SROW + col) * 2;
                asm volatile("ldmatrix.sync.aligned.m8n8.x4.shared.b16 {%0,%1,%2,%3}, [%4];"
                             : "=r"(a[wm][0]), "=r"(a[wm][1]), "=r"(a[wm][2]), "=r"(a[wm][3])
                             : "r"(addr));
            }
            uint32_t b[8][2];
#pragma unroll
            for (int p = 0; p < 4; p++) {
                int n = warp_n * 64 + p * 16 + (lane & 7) + ((lane >> 4) << 3);
                int col = kk + (((lane >> 3) & 1) << 3);
                uint32_t addr = baseB + (uint32_t)(n * SROW + col) * 2;
                uint32_t r0, r1, r2, r3;
                asm volatile("ldmatrix.sync.aligned.m8n8.x4.shared.b16 {%0,%1,%2,%3}, [%4];"
                             : "=r"(r0), "=r"(r1), "=r"(r2), "=r"(r3) : "r"(addr));
                b[2 * p][0] = r0; b[2 * p][1] = r1;
                b[2 * p + 1][0] = r2; b[2 * p + 1][1] = r3;
            }
#pragma unroll
            for (int wm = 0; wm < 2; wm++)
#pragma unroll
                for (int wn = 0; wn < 8; wn++)
                    asm volatile(
                        "mma.sync.aligned.m16n8k16.row.col.f32.f16.f16.f32 "
                        "{%0,%1,%2,%3}, {%4,%5,%6,%7}, {%8,%9}, {%0,%1,%2,%3};"
                        : "+f"(acc[wm][wn][0]), "+f"(acc[wm][wn][1]),
                          "+f"(acc[wm][wn][2]), "+f"(acc[wm][wn][3])
                        : "r"(a[wm][0]), "r"(a[wm][1]), "r"(a[wm][2]), "r"(a[wm][3]),
                          "r"(b[wn][0]), "r"(b[wn][1]));
        }
        __syncthreads();
    }

    // Epilogue
    float* Cf = (float*)Cv;
    __half* Ch = (__half*)Cv;
#pragma unroll
    for (int wm = 0; wm < 2; wm++) {
        int r = m0 + warp_m * 32 + wm * 16 + (lane >> 2);
#pragma unroll
        for (int wn = 0; wn < 8; wn++) {
            int c = n0 + warp_n * 64 + wn * 8 + ((lane & 3) << 1);
            float b0 = 0.f, b1 = 0.f;
            if (bias) { b0 = bias[c]; b1 = bias[c + 1]; }
            if (r < M) {
                float v0 = acc[wm][wn][0] + b0, v1 = acc[wm][wn][1] + b1;
                if (HALF_OUT)
                    *(__half2*)(Ch + (size_t)r * ldc + c) = __floats2half2_rn(v0, v1);
                else
                    *(float2*)(Cf + (size_t)r * ldc + c) = make_float2(v0, v1);
            }
            if (r + 8 < M) {
                float v0 = acc[wm][wn][2] + b0, v1 = acc[wm][wn][3] + b1;
                if (HALF_OUT)
                    *(__half2*)(Ch + (size_t)(r + 8) * ldc + c) = __floats2half2_rn(v0, v1);
                else
                    *(float2*)(Cf + (size_t)(r + 8) * ldc + c) = make_float2(v0, v1);
            }
        }
    }
}

// ---------------------------------------------------------------------------
// Conversions
// ---------------------------------------------------------------------------
__global__ void tohalf_kernel(const float4* __restrict__ x, __half2* __restrict__ o, int n4)
{
    int i = blockIdx.x * blockDim.x + threadIdx.x;
    if (i >= n4) return;
    float4 v = x[i];
    o[2 * i]     = __floats2half2_rn(v.x, v.y);
    o[2 * i + 1] = __floats2half2_rn(v.z, v.w);
}

// W[K x N] (fp32, row-major) -> T[N x K] (fp16)
__global__ void transpose_half_kernel(const float* __restrict__ W, int K, int N,
                                      __half* __restrict__ T)
{
    int idx = blockIdx.x * blockDim.x + threadIdx.x;
    if (idx >= K * N) return;
    int n = idx % N, k = idx / N;
    T[(size_t)n * K + k] = __float2half(W[(size_t)k * N + n]);
}

// out[col_off + c] = sum_k b[k] * W[k*ldw + c]
__global__ void vecmat_kernel(const float* __restrict__ b, const float* __restrict__ W,
                              int K, int ldw, float* __restrict__ out, int n, int col_off)
{
    int c = blockIdx.x * blockDim.x + threadIdx.x;
    if (c >= n) return;
    float a = 0.f;
    for (int k = 0; k < K; k++) a += b[k] * W[(size_t)k * ldw + c];
    out[col_off + c] = a;
}

// ---------------------------------------------------------------------------
// CSR build
// ---------------------------------------------------------------------------
__global__ void count_kernel(const int* __restrict__ dst, int E, int* __restrict__ cnt)
{
    int e = blockIdx.x * blockDim.x + threadIdx.x;
    if (e < E) atomicAdd(&cnt[dst[e]], 1);
}

__global__ void scan_kernel(const int* __restrict__ cnt, int* __restrict__ rowstart, int n)
{
    __shared__ int warp_sums[32];
    __shared__ int s_carry;
    int tid = threadIdx.x, lane = tid & 31, wid = tid >> 5;
    if (tid == 0) s_carry = 0;
    __syncthreads();
    for (int base = 0; base < n; base += 1024) {
        int i = base + tid;
        int v = (i < n) ? cnt[i] : 0;
        int x = v;
#pragma unroll
        for (int off = 1; off < 32; off <<= 1) {
            int y = __shfl_up_sync(0xffffffffu, x, off);
            if (lane >= off) x += y;
        }
        if (lane == 31) warp_sums[wid] = x;
        __syncthreads();
        if (wid == 0) {
            int w = warp_sums[lane];
#pragma unroll
            for (int off = 1; off < 32; off <<= 1) {
                int y = __shfl_up_sync(0xffffffffu, w, off);
                if (lane >= off) w += y;
            }
            warp_sums[lane] = w;
        }
        __syncthreads();
        int warp_off = (wid > 0) ? warp_sums[wid - 1] : 0;
        int incl = x + warp_off;
        int carry = s_carry;
        if (i < n) rowstart[i] = carry + incl - v;
        __syncthreads();
        if (tid == 1023) s_carry = carry + incl;
        __syncthreads();
    }
    if (tid == 0) rowstart[n] = s_carry;
}

__global__ void copy_int_kernel(const int* __restrict__ s, int* __restrict__ d, int n)
{
    int i = blockIdx.x * blockDim.x + threadIdx.x;
    if (i < n) d[i] = s[i];
}

__global__ void fill_kernel(const int* __restrict__ src, const int* __restrict__ dst,
                            int E, int* __restrict__ cursor, int* __restrict__ csr)
{
    int e = blockIdx.x * blockDim.x + threadIdx.x;
    if (e < E) {
        int p = atomicAdd(&cursor[dst[e]], 1);
        csr[p] = src[e];
    }
}

// ---------------------------------------------------------------------------
// Fused mean-aggregate + bias + residual + ReLU; fp16 gather source, fp16 out
// out(r,c) = relu( mean_{s in row r} S[s,c] + bias[c] + other[r,c] )
// ---------------------------------------------------------------------------
__global__ void __launch_bounds__(HID)
aggregate_kernel(const int* __restrict__ rowstart, const int* __restrict__ csr,
                 const __half* __restrict__ S, int ldS,
                 const float* __restrict__ other, int ldO,
                 const float* __restrict__ bias,
                 __half* __restrict__ out)
{
    int r = blockIdx.x;
    int c = threadIdx.x;
    int s = rowstart[r], e = rowstart[r + 1];
    float accum = 0.f;
    for (int i = s; i < e; i++) {
        int srcRow = csr[i];
        accum += __half2float(S[(size_t)srcRow * ldS + c]);
    }
    float m = accum / fmaxf((float)(e - s), 1.0f);
    float v = fmaxf(m + bias[c] + other[(size_t)r * ldO + c], 0.0f);
    out[(size_t)r * HID + c] = __float2half(v);
}

// ---------------------------------------------------------------------------
// Host helpers
// ---------------------------------------------------------------------------
static inline void gemm_f32(int M, int N, int K, const __half* A, const __half* B,
                            float* C, int ldc, const float* bias)
{
    dim3 g((M + GM - 1) / GM, N / GN);
    mma_gemm_kernel<false><<<g, 256>>>(M, N, K, A, B, (void*)C, ldc, bias);
}
static inline void gemm_f16(int M, int N, int K, const __half* A, const __half* B,
                            __half* C, int ldc, const float* bias)
{
    dim3 g((M + GM - 1) / GM, N / GN);
    mma_gemm_kernel<true><<<g, 256>>>(M, N, K, A, B, (void*)C, ldc, bias);
}
static inline void tohalf(const float* x, __half* o, size_t n)
{
    int n4 = (int)(n / 4);
    tohalf_kernel<<<(n4 + 255) / 256, 256>>>((const float4*)x, (__half2*)o, n4);
}

static inline void process_edges(const int* e_base, int E,
                                 int* cnt, int* rowstart, int* cursor, int* csr,
                                 const __half* S, int ldS,
                                 const float* other, int ldO,
                                 const float* bias, __half* out)
{
    const int* src = e_base;
    const int* dst = e_base + E;
    cudaMemsetAsync(cnt, 0, NROWS * sizeof(int));
    count_kernel<<<(E + 255) / 256, 256>>>(dst, E, cnt);
    scan_kernel<<<1, 1024>>>(cnt, rowstart, NROWS);
    copy_int_kernel<<<(NROWS + 255) / 256, 256>>>(rowstart, cursor, NROWS);
    fill_kernel<<<(E + 255) / 256, 256>>>(src, dst, E, cursor, csr);
    aggregate_kernel<<<NROWS, HID>>>(rowstart, csr, S, ldS, other, ldO, bias, out);
}

extern "C" void kernel_launch(void* const* d_in, const int* in_sizes, int n_in,
                              void* d_out, int out_size)
{
    const float* article_x   = (const float*)d_in[0];
    const float* community_x = (const float*)d_in[1];
    const int*   e_wb        = (const int*)d_in[2];
    const int*   e_mb        = (const int*)d_in[3];
    const int*   e_int       = (const int*)d_in[4];
    const float* W1  = (const float*)d_in[5];
    const float* b1  = (const float*)d_in[6];
    const float* W2  = (const float*)d_in[7];
    const float* b2  = (const float*)d_in[8];
    const float* Wl1 = (const float*)d_in[9];
    const float* bl1 = (const float*)d_in[10];
    const float* Wr1 = (const float*)d_in[11];
    const float* Wl2 = (const float*)d_in[12];
    const float* bl2 = (const float*)d_in[13];
    const float* Wr2 = (const float*)d_in[14];
    const float* Wl3 = (const float*)d_in[15];
    const float* bl3 = (const float*)d_in[16];
    const float* Wr3 = (const float*)d_in[17];
    const float* W3  = (const float*)d_in[18];
    const float* b3  = (const float*)d_in[19];

    const int E_wb  = in_sizes[2] / 2;
    const int E_mb  = in_sizes[3] / 2;
    const int E_int = in_sizes[4] / 2;

    unsigned char* arena;
    cudaGetSymbolAddress((void**)&arena, g_arena);
#define AP(T, off) ((T*)(arena + (off)))
    __half *AxH  = AP(__half, OFF_AXH),  *CxH  = AP(__half, OFF_CXH);
    __half *A12H = AP(__half, OFF_A12H);
    float  *CC   = AP(float, OFF_CC),    *h1r  = AP(float, OFF_H1R);
    __half *tH   = AP(__half, OFF_TH);
    __half *h1H  = AP(__half, OFF_H1H), *h2H = AP(__half, OFF_H2H), *h3H = AP(__half, OFF_H3H);
    __half *W1H  = AP(__half, OFF_W1H), *W2H = AP(__half, OFF_W2H);
    __half *Wl1t = AP(__half, OFF_WL1T), *Wl2t = AP(__half, OFF_WL2T), *Wr1t = AP(__half, OFF_WR1T);
    __half *WAt  = AP(__half, OFF_WAT),  *WCt  = AP(__half, OFF_WCT);
    __half *Wr2t = AP(__half, OFF_WR2T), *Wl3t = AP(__half, OFF_WL3T), *W3t = AP(__half, OFF_W3T);
    float  *bA   = AP(float, OFF_BA),    *bC   = AP(float, OFF_BC);
    int *cnt = AP(int, OFF_CNT), *cursor = AP(int, OFF_CURSOR);
    int *csr = AP(int, OFF_CSR), *rowstart = AP(int, OFF_ROWST);

    // ---- weight conversions (fp32 -> fp16, transposed for B operand) ----
    tohalf(W1, W1H, (size_t)F_IN * PROJ);
    tohalf(W2, W2H, (size_t)F_IN * PROJ);
    transpose_half_kernel<<<(PROJ * HID + 255) / 256, 256>>>(Wl1, PROJ, HID, Wl1t);
    transpose_half_kernel<<<(PROJ * HID + 255) / 256, 256>>>(Wl2, PROJ, HID, Wl2t);
    transpose_half_kernel<<<(PROJ * HID + 255) / 256, 256>>>(Wr1, PROJ, HID, Wr1t);
    transpose_half_kernel<<<(HID * HID + 255) / 256, 256>>>(Wr2, HID, HID, Wr2t);
    transpose_half_kernel<<<(HID * HID + 255) / 256, 256>>>(Wl3, HID, HID, Wl3t);
    transpose_half_kernel<<<(HID * OUTD + 255) / 256, 256>>>(W3, HID, OUTD, W3t);
    // Wr3^T goes straight into rows 256..511 of WCt
    transpose_half_kernel<<<(F_IN * HID + 255) / 256, 256>>>(Wr3, F_IN, HID,
                                                             WCt + (size_t)256 * F_IN);

    // ---- weight folds on tensor cores (outputs are (W@Wl)^T, fp16) ----
    // D[256,768] = Wl1t[256,1024] @ W1H[768,1024]^T = (W1@Wl1)^T
    gemm_f16(HID, F_IN, PROJ, Wl1t, W1H, WAt,                      F_IN, nullptr);
    gemm_f16(HID, F_IN, PROJ, Wl2t, W1H, WAt + (size_t)256 * F_IN, F_IN, nullptr);
    gemm_f16(HID, F_IN, PROJ, Wr1t, W2H, WCt,                      F_IN, nullptr);

    // ---- bias folds (fp32) ----
    cudaMemsetAsync(bC, 0, 512 * sizeof(float));
    vecmat_kernel<<<1, 256>>>(b1, Wl1, PROJ, HID, bA, HID, 0);
    vecmat_kernel<<<1, 256>>>(b1, Wl2, PROJ, HID, bA, HID, HID);
    vecmat_kernel<<<1, 256>>>(b2, Wr1, PROJ, HID, bC, HID, 0);

    // ---- activation conversions ----
    tohalf(article_x,   AxH, NR * F_IN);
    tohalf(community_x, CxH, NR * F_IN);

    // ---- big projections ----
    // A12H = article_x @ [W1Wl1 | W1Wl2] + bA     (fp16 out: gather source)
    gemm_f16(NROWS, 512, F_IN, AxH, WAt, A12H, 512, bA);
    // CC   = community_x @ [W2Wr1 | Wr3] + bC     (fp32 out: streamed addend)
    gemm_f32(NROWS, 512, F_IN, CxH, WCt, CC, 512, bC);

    // ---- conv1: h1 = relu(mean(A1[src]) + bl1 + C1) ----
    process_edges(e_wb, E_wb, cnt, rowstart, cursor, csr,
                  A12H, 512, CC, 512, bl1, h1H);

    // ---- conv2: h2 = relu(mean(A2[src]) + bl2 + h1@Wr2) ----
    gemm_f32(NROWS, HID, HID, h1H, Wr2t, h1r, HID, nullptr);
    process_edges(e_mb, E_mb, cnt, rowstart, cursor, csr,
                  A12H + HID, 512, h1r, HID, bl2, h2H);

    // ---- conv3: h3 = relu(mean((h2@Wl3)[src]) + bl3 + community_x@Wr3) ----
    gemm_f16(NROWS, HID, HID, h2H, Wl3t, tH, HID, nullptr);
    process_edges(e_int, E_int, cnt, rowstart, cursor, csr,
                  tH, 256, CC + HID, 512, bl3, h3H);

    // ---- out = h3 @ W3 + b3 (fp32 to d_out) ----
    gemm_f32(NROWS, OUTD, HID, h3H, W3t, (float*)d_out, OUTD, b3);
}

// round 6
// speedup vs baseline: 4.2369x; 1.4849x over previous
#include <cuda_runtime.h>
#include <cuda_fp16.h>
#include <cstdint>

// ---------------------------------------------------------------------------
// Problem constants
// ---------------------------------------------------------------------------
#define NROWS   50000
#define F_IN    768
#define PROJ    1024
#define HID     256
#define OUTD    128
#define NR ((size_t)NROWS)
#define EMAX_TOT 900000

// ---------------------------------------------------------------------------
// Arena of static device scratch (no runtime allocation allowed)
// ---------------------------------------------------------------------------
constexpr size_t OFF_AXH   = 0;                                   // half [NR x 768]
constexpr size_t OFF_CXH   = OFF_AXH + NR * F_IN * 2;             // half [NR x 768]
constexpr size_t OFF_A12H  = OFF_CXH + NR * F_IN * 2;             // half [NR x 512]
constexpr size_t OFF_CC    = OFF_A12H + NR * 512 * 2;             // fp32 [NR x 512]
constexpr size_t OFF_H1R   = OFF_CC + NR * 512 * 4;               // fp32 [NR x 256]
constexpr size_t OFF_TH    = OFF_H1R + NR * HID * 4;              // half [NR x 256]
constexpr size_t OFF_H1H   = OFF_TH + NR * HID * 2;               // half [NR x 256]
constexpr size_t OFF_H2H   = OFF_H1H + NR * HID * 2;
constexpr size_t OFF_H3H   = OFF_H2H + NR * HID * 2;
constexpr size_t OFF_W1H   = OFF_H3H + NR * HID * 2;              // half [768 x 1024]
constexpr size_t OFF_W2H   = OFF_W1H + (size_t)F_IN * PROJ * 2;
constexpr size_t OFF_WL1T  = OFF_W2H + (size_t)F_IN * PROJ * 2;   // half [256 x 1024]
constexpr size_t OFF_WL2T  = OFF_WL1T + (size_t)HID * PROJ * 2;   // contiguous after WL1T!
constexpr size_t OFF_WR1T  = OFF_WL2T + (size_t)HID * PROJ * 2;
constexpr size_t OFF_WAT   = OFF_WR1T + (size_t)HID * PROJ * 2;   // half [512 x 768]
constexpr size_t OFF_WCT   = OFF_WAT + (size_t)512 * F_IN * 2;    // half [512 x 768]
constexpr size_t OFF_WR2T  = OFF_WCT + (size_t)512 * F_IN * 2;    // half [256 x 256]
constexpr size_t OFF_WL3T  = OFF_WR2T + (size_t)HID * HID * 2;
constexpr size_t OFF_W3T   = OFF_WL3T + (size_t)HID * HID * 2;    // half [128 x 256]
constexpr size_t OFF_BA    = OFF_W3T + (size_t)OUTD * HID * 2;    // fp32 [512]
constexpr size_t OFF_BC    = OFF_BA + 512 * 4;                    // fp32 [512]
constexpr size_t OFF_CNT   = OFF_BC + 512 * 4;                    // int [3 x 50000]
constexpr size_t OFF_ROWST = OFF_CNT + 3 * NR * 4;                // int [3 x 50001]
constexpr size_t OFF_CURSOR= OFF_ROWST + 3 * (NR + 1) * 4;        // int [3 x 50000]
constexpr size_t OFF_CSR   = OFF_CURSOR + 3 * NR * 4;             // int [900000]
constexpr size_t ARENA_TOTAL = OFF_CSR + (size_t)EMAX_TOT * 4 + 64;

__device__ unsigned char g_arena[ARENA_TOTAL];

__device__ __forceinline__ uint32_t smem_u32(const void* p) {
    uint32_t a;
    asm("{ .reg .u64 t; cvta.to.shared.u64 t, %1; cvt.u32.u64 %0, t; }" : "=r"(a) : "l"(p));
    return a;
}

// ---------------------------------------------------------------------------
// Tensor-core GEMM via mma.sync:
//   C[M,N] = A[M,K](fp16) @ B[N,K](fp16)^T  (+bias), fp32 accumulate.
// Tile 128x128x32, 8 warps (4Mx2N), 3-stage cp.async pipeline (dynamic smem).
// smem rows padded to 40 halfs (80B stride -> conflict-free ldmatrix).
// Requires: N % 128 == 0, K % 32 == 0. M arbitrary.
// ---------------------------------------------------------------------------
#define GM 128
#define GN 128
#define GK 32
#define SROW 40
#define STAGES 3
#define ABYTES (GM * SROW * 2)          // 10240
#define STAGE_BYTES (2 * ABYTES)        // A + B per stage
#define GEMM_SMEM (STAGES * STAGE_BYTES)  // 61440

template<bool HALF_OUT>
__global__ void __launch_bounds__(256)
mma_gemm_kernel(int M, int N, int K,
                const __half* __restrict__ A,
                const __half* __restrict__ B,
                void* __restrict__ Cv, int ldc,
                const float* __restrict__ bias)
{
    extern __shared__ __align__(16) char dynsmem[];
    const uint32_t sbase = smem_u32(dynsmem);

    const int tid = threadIdx.x;
    const int lane = tid & 31, wid = tid >> 5;
    const int warp_m = wid >> 1, warp_n = wid & 1;
    const int m0 = blockIdx.x * GM, n0 = blockIdx.y * GN;
    const int nk = K / GK;

    float acc[2][8][4];
#pragma unroll
    for (int i = 0; i < 2; i++)
#pragma unroll
        for (int j = 0; j < 8; j++)
#pragma unroll
            for (int q = 0; q < 4; q++) acc[i][j][q] = 0.f;

    auto issue = [&](int ch) {
        int st = ch % STAGES;
        int k0 = ch * GK;
        uint32_t baseA = sbase + st * STAGE_BYTES;
        uint32_t baseB = baseA + ABYTES;
#pragma unroll
        for (int i = 0; i < 2; i++) {
            int idx = tid + i * 256;          // 0..511
            int row = idx >> 2;               // 0..127
            int c8  = (idx & 3) << 3;         // 0,8,16,24
            uint32_t soff = (uint32_t)(row * SROW + c8) * 2;
            int gr = m0 + row;
            const __half* ga = A + (size_t)(gr < M ? gr : 0) * K + k0 + c8;
            int sz = (gr < M) ? 16 : 0;
            asm volatile("cp.async.cg.shared.global [%0], [%1], 16, %2;"
                         :: "r"(baseA + soff), "l"(ga), "r"(sz));
            const __half* gb = B + (size_t)(n0 + row) * K + k0 + c8;
            asm volatile("cp.async.cg.shared.global [%0], [%1], 16;"
                         :: "r"(baseB + soff), "l"(gb));
        }
        asm volatile("cp.async.commit_group;");
    };

    issue(0);
    if (nk > 1) issue(1);

    for (int ch = 0; ch < nk; ch++) {
        if (ch + 1 < nk) asm volatile("cp.async.wait_group 1;");
        else             asm volatile("cp.async.wait_group 0;");
        __syncthreads();
        if (ch + 2 < nk) issue(ch + 2);

        int st = ch % STAGES;
        uint32_t baseA = sbase + st * STAGE_BYTES;
        uint32_t baseB = baseA + ABYTES;
#pragma unroll
        for (int ks = 0; ks < 2; ks++) {
            int kk = ks * 16;
            uint32_t a[2][4];
#pragma unroll
            for (int wm = 0; wm < 2; wm++) {
                int row = warp_m * 32 + wm * 16 + (lane & 15);
                int col = kk + ((lane >> 4) << 3);
                uint32_t addr = baseA + (uint32_t)(row * SROW + col) * 2;
                asm volatile("ldmatrix.sync.aligned.m8n8.x4.shared.b16 {%0,%1,%2,%3}, [%4];"
                             : "=r"(a[wm][0]), "=r"(a[wm][1]), "=r"(a[wm][2]), "=r"(a[wm][3])
                             : "r"(addr));
            }
            uint32_t b[8][2];
#pragma unroll
            for (int p = 0; p < 4; p++) {
                int n = warp_n * 64 + p * 16 + (lane & 7) + ((lane >> 4) << 3);
                int col = kk + (((lane >> 3) & 1) << 3);
                uint32_t addr = baseB + (uint32_t)(n * SROW + col) * 2;
                uint32_t r0, r1, r2, r3;
                asm volatile("ldmatrix.sync.aligned.m8n8.x4.shared.b16 {%0,%1,%2,%3}, [%4];"
                             : "=r"(r0), "=r"(r1), "=r"(r2), "=r"(r3) : "r"(addr));
                b[2 * p][0] = r0; b[2 * p][1] = r1;
                b[2 * p + 1][0] = r2; b[2 * p + 1][1] = r3;
            }
#pragma unroll
            for (int wm = 0; wm < 2; wm++)
#pragma unroll
                for (int wn = 0; wn < 8; wn++)
                    asm volatile(
                        "mma.sync.aligned.m16n8k16.row.col.f32.f16.f16.f32 "
                        "{%0,%1,%2,%3}, {%4,%5,%6,%7}, {%8,%9}, {%0,%1,%2,%3};"
                        : "+f"(acc[wm][wn][0]), "+f"(acc[wm][wn][1]),
                          "+f"(acc[wm][wn][2]), "+f"(acc[wm][wn][3])
                        : "r"(a[wm][0]), "r"(a[wm][1]), "r"(a[wm][2]), "r"(a[wm][3]),
                          "r"(b[wn][0]), "r"(b[wn][1]));
        }
        __syncthreads();
    }

    // Epilogue
    float* Cf = (float*)Cv;
    __half* Ch = (__half*)Cv;
#pragma unroll
    for (int wm = 0; wm < 2; wm++) {
        int r = m0 + warp_m * 32 + wm * 16 + (lane >> 2);
#pragma unroll
        for (int wn = 0; wn < 8; wn++) {
            int c = n0 + warp_n * 64 + wn * 8 + ((lane & 3) << 1);
            float b0 = 0.f, b1 = 0.f;
            if (bias) { b0 = bias[c]; b1 = bias[c + 1]; }
            if (r < M) {
                float v0 = acc[wm][wn][0] + b0, v1 = acc[wm][wn][1] + b1;
                if (HALF_OUT)
                    *(__half2*)(Ch + (size_t)r * ldc + c) = __floats2half2_rn(v0, v1);
                else
                    *(float2*)(Cf + (size_t)r * ldc + c) = make_float2(v0, v1);
            }
            if (r + 8 < M) {
                float v0 = acc[wm][wn][2] + b0, v1 = acc[wm][wn][3] + b1;
                if (HALF_OUT)
                    *(__half2*)(Ch + (size_t)(r + 8) * ldc + c) = __floats2half2_rn(v0, v1);
                else
                    *(float2*)(Cf + (size_t)(r + 8) * ldc + c) = make_float2(v0, v1);
            }
        }
    }
}

// ---------------------------------------------------------------------------
// Dual fp32->fp16 conversion (two tensors, one launch)
// ---------------------------------------------------------------------------
__global__ void tohalf2_kernel(const float4* __restrict__ x0, __half2* __restrict__ o0,
                               const float4* __restrict__ x1, __half2* __restrict__ o1,
                               int n4)
{
    int i = blockIdx.x * blockDim.x + threadIdx.x;
    const float4* x; __half2* o; int j;
    if (i < n4)          { x = x0; o = o0; j = i; }
    else if (i < 2 * n4) { x = x1; o = o1; j = i - n4; }
    else return;
    float4 v = x[j];
    o[2 * j]     = __floats2half2_rn(v.x, v.y);
    o[2 * j + 1] = __floats2half2_rn(v.z, v.w);
}

// ---------------------------------------------------------------------------
// Batched prep: 7 transposes (fp32 [KxN] -> fp16 [NxK]) + 3 bias folds + zero
// Job table is compile-time.
// ---------------------------------------------------------------------------
__device__ __forceinline__ void tjob(const float* __restrict__ W, __half* __restrict__ T,
                                     int K, int N, int local)
{
    int k = local / N, n = local % N;
    T[(size_t)n * K + k] = __float2half(W[local]);
}
__device__ __forceinline__ void vjob(const float* __restrict__ b, const float* __restrict__ W,
                                     float* __restrict__ out, int K, int c)
{
    float a0 = 0.f, a1 = 0.f, a2 = 0.f, a3 = 0.f;
    for (int k = 0; k < K; k += 4) {
        a0 += b[k]     * W[(size_t)k * 256 + c];
        a1 += b[k + 1] * W[(size_t)(k + 1) * 256 + c];
        a2 += b[k + 2] * W[(size_t)(k + 2) * 256 + c];
        a3 += b[k + 3] * W[(size_t)(k + 3) * 256 + c];
    }
    out[c] = (a0 + a1) + (a2 + a3);
}

#define TBLOCKS 4480   // 1146880 / 256

__global__ void prep_kernel(
    const float* Wl1, const float* Wl2, const float* Wr1,
    const float* Wr2, const float* Wl3, const float* W3, const float* Wr3,
    __half* Wl1t, __half* Wl2t, __half* Wr1t,
    __half* Wr2t, __half* Wl3t, __half* W3t, __half* Wr3t,
    const float* b1, const float* b2, float* bA, float* bC)
{
    int blk = blockIdx.x;
    if (blk < TBLOCKS) {
        int t = blk * 256 + threadIdx.x;
        if      (t <  262144) tjob(Wl1, Wl1t, 1024, 256, t);
        else if (t <  524288) tjob(Wl2, Wl2t, 1024, 256, t - 262144);
        else if (t <  786432) tjob(Wr1, Wr1t, 1024, 256, t - 524288);
        else if (t <  851968) tjob(Wr2, Wr2t,  256, 256, t - 786432);
        else if (t <  917504) tjob(Wl3, Wl3t,  256, 256, t - 851968);
        else if (t <  950272) tjob(W3,  W3t,   256, 128, t - 917504);
        else                  tjob(Wr3, Wr3t,  768, 256, t - 950272);
    } else {
        int which = blk - TBLOCKS;
        int c = threadIdx.x;
        if (which == 0) vjob(b1, Wl1, bA, 1024, c);
        else if (which == 1) vjob(b1, Wl2, bA + 256, 1024, c);
        else { vjob(b2, Wr1, bC, 1024, c); bC[256 + c] = 0.f; }
    }
}

// ---------------------------------------------------------------------------
// CSR build for all 3 graphs, batched
// ---------------------------------------------------------------------------
__global__ void count3_kernel(const int* __restrict__ e0, int E0,
                              const int* __restrict__ e1, int E1,
                              const int* __restrict__ e2, int E2,
                              int* __restrict__ cnt)
{
    int t = blockIdx.x * blockDim.x + threadIdx.x;
    if (t < E0)                atomicAdd(&cnt[e0[E0 + t]], 1);
    else if (t < E0 + E1)      atomicAdd(&cnt[NROWS + e1[E1 + (t - E0)]], 1);
    else if (t < E0 + E1 + E2) atomicAdd(&cnt[2 * NROWS + e2[E2 + (t - E0 - E1)]], 1);
}

// one block per graph; exclusive scan of 50000 counts, writes rowstart + cursor
__global__ void scan3_kernel(const int* __restrict__ cnt,
                             int* __restrict__ rowstart, int* __restrict__ cursor)
{
    __shared__ int warp_sums[32];
    __shared__ int s_carry;
    int g = blockIdx.x;
    const int* c = cnt + (size_t)g * NROWS;
    int* rs = rowstart + (size_t)g * (NROWS + 1);
    int* cu = cursor + (size_t)g * NROWS;
    int tid = threadIdx.x, lane = tid & 31, wid = tid >> 5;
    if (tid == 0) s_carry = 0;
    __syncthreads();
    for (int base = 0; base < NROWS; base += 1024) {
        int i = base + tid;
        int v = (i < NROWS) ? c[i] : 0;
        int x = v;
#pragma unroll
        for (int off = 1; off < 32; off <<= 1) {
            int y = __shfl_up_sync(0xffffffffu, x, off);
            if (lane >= off) x += y;
        }
        if (lane == 31) warp_sums[wid] = x;
        __syncthreads();
        if (wid == 0) {
            int w = warp_sums[lane];
#pragma unroll
            for (int off = 1; off < 32; off <<= 1) {
                int y = __shfl_up_sync(0xffffffffu, w, off);
                if (lane >= off) w += y;
            }
            warp_sums[lane] = w;
        }
        __syncthreads();
        int warp_off = (wid > 0) ? warp_sums[wid - 1] : 0;
        int incl = x + warp_off;
        int carry = s_carry;
        if (i < NROWS) { int ex = carry + incl - v; rs[i] = ex; cu[i] = ex; }
        __syncthreads();
        if (tid == 1023) s_carry = carry + incl;
        __syncthreads();
    }
    if (tid == 0) rs[NROWS] = s_carry;
}

__global__ void fill3_kernel(const int* __restrict__ e0, int E0,
                             const int* __restrict__ e1, int E1,
                             const int* __restrict__ e2, int E2,
                             int* __restrict__ cursor, int* __restrict__ csr)
{
    int t = blockIdx.x * blockDim.x + threadIdx.x;
    if (t < E0) {
        int p = atomicAdd(&cursor[e0[E0 + t]], 1);
        csr[p] = e0[t];
    } else if (t < E0 + E1) {
        int j = t - E0;
        int p = atomicAdd(&cursor[NROWS + e1[E1 + j]], 1);
        csr[E0 + p] = e1[j];
    } else if (t < E0 + E1 + E2) {
        int j = t - E0 - E1;
        int p = atomicAdd(&cursor[2 * NROWS + e2[E2 + j]], 1);
        csr[E0 + E1 + p] = e2[j];
    }
}

// ---------------------------------------------------------------------------
// Fused mean-aggregate + bias + residual + ReLU (half2 wide, unroll-4 MLP)
// out(r,:) = relu( mean_{s in row r} S[s,:] + bias + other[r,:] ), fp16 out
// ---------------------------------------------------------------------------
__global__ void __launch_bounds__(128)
aggregate_kernel(const int* __restrict__ rowstart, const int* __restrict__ csr,
                 const __half2* __restrict__ S2, int ldS2,
                 const float* __restrict__ other, int ldO,
                 const float* __restrict__ bias,
                 __half2* __restrict__ out2)
{
    int r = blockIdx.x;
    int c2 = threadIdx.x;
    int s = rowstart[r], e = rowstart[r + 1];
    float ax = 0.f, ay = 0.f, bx = 0.f, by = 0.f;
    int i = s;
    for (; i + 4 <= e; i += 4) {
        int i0 = csr[i], i1 = csr[i + 1], i2 = csr[i + 2], i3 = csr[i + 3];
        float2 v0 = __half22float2(S2[(size_t)i0 * ldS2 + c2]);
        float2 v1 = __half22float2(S2[(size_t)i1 * ldS2 + c2]);
        float2 v2 = __half22float2(S2[(size_t)i2 * ldS2 + c2]);
        float2 v3 = __half22float2(S2[(size_t)i3 * ldS2 + c2]);
        ax += v0.x + v1.x; ay += v0.y + v1.y;
        bx += v2.x + v3.x; by += v2.y + v3.y;
    }
    for (; i < e; i++) {
        float2 v = __half22float2(S2[(size_t)csr[i] * ldS2 + c2]);
        ax += v.x; ay += v.y;
    }
    float inv = 1.f / fmaxf((float)(e - s), 1.f);
    float2 oth = *(const float2*)(other + (size_t)r * ldO + 2 * c2);
    float bb0 = bias[2 * c2], bb1 = bias[2 * c2 + 1];
    float vx = fmaxf((ax + bx) * inv + bb0 + oth.x, 0.f);
    float vy = fmaxf((ay + by) * inv + bb1 + oth.y, 0.f);
    out2[(size_t)r * 128 + c2] = __floats2half2_rn(vx, vy);
}

// ---------------------------------------------------------------------------
// Host helpers
// ---------------------------------------------------------------------------
static inline void gemm_f32(int M, int N, int K, const __half* A, const __half* B,
                            float* C, int ldc, const float* bias)
{
    dim3 g((M + GM - 1) / GM, N / GN);
    mma_gemm_kernel<false><<<g, 256, GEMM_SMEM>>>(M, N, K, A, B, (void*)C, ldc, bias);
}
static inline void gemm_f16(int M, int N, int K, const __half* A, const __half* B,
                            __half* C, int ldc, const float* bias)
{
    dim3 g((M + GM - 1) / GM, N / GN);
    mma_gemm_kernel<true><<<g, 256, GEMM_SMEM>>>(M, N, K, A, B, (void*)C, ldc, bias);
}

extern "C" void kernel_launch(void* const* d_in, const int* in_sizes, int n_in,
                              void* d_out, int out_size)
{
    const float* article_x   = (const float*)d_in[0];
    const float* community_x = (const float*)d_in[1];
    const int*   e_wb        = (const int*)d_in[2];
    const int*   e_mb        = (const int*)d_in[3];
    const int*   e_int       = (const int*)d_in[4];
    const float* W1  = (const float*)d_in[5];
    const float* b1  = (const float*)d_in[6];
    const float* W2  = (const float*)d_in[7];
    const float* b2  = (const float*)d_in[8];
    const float* Wl1 = (const float*)d_in[9];
    const float* bl1 = (const float*)d_in[10];
    const float* Wr1 = (const float*)d_in[11];
    const float* Wl2 = (const float*)d_in[12];
    const float* bl2 = (const float*)d_in[13];
    const float* Wr2 = (const float*)d_in[14];
    const float* Wl3 = (const float*)d_in[15];
    const float* bl3 = (const float*)d_in[16];
    const float* Wr3 = (const float*)d_in[17];
    const float* W3  = (const float*)d_in[18];
    const float* b3  = (const float*)d_in[19];

    const int E0 = in_sizes[2] / 2;   // e_wb
    const int E1 = in_sizes[3] / 2;   // e_mb
    const int E2 = in_sizes[4] / 2;   // e_int

    static bool attr_set = false;
    cudaFuncSetAttribute(mma_gemm_kernel<false>,
                         cudaFuncAttributeMaxDynamicSharedMemorySize, GEMM_SMEM);
    cudaFuncSetAttribute(mma_gemm_kernel<true>,
                         cudaFuncAttributeMaxDynamicSharedMemorySize, GEMM_SMEM);
    (void)attr_set;

    unsigned char* arena;
    cudaGetSymbolAddress((void**)&arena, g_arena);
#define AP(T, off) ((T*)(arena + (off)))
    __half *AxH  = AP(__half, OFF_AXH),  *CxH  = AP(__half, OFF_CXH);
    __half *A12H = AP(__half, OFF_A12H);
    float  *CC   = AP(float, OFF_CC),    *h1r  = AP(float, OFF_H1R);
    __half *tH   = AP(__half, OFF_TH);
    __half *h1H  = AP(__half, OFF_H1H), *h2H = AP(__half, OFF_H2H), *h3H = AP(__half, OFF_H3H);
    __half *W1H  = AP(__half, OFF_W1H), *W2H = AP(__half, OFF_W2H);
    __half *Wl1t = AP(__half, OFF_WL1T), *Wl2t = AP(__half, OFF_WL2T), *Wr1t = AP(__half, OFF_WR1T);
    __half *WAt  = AP(__half, OFF_WAT),  *WCt  = AP(__half, OFF_WCT);
    __half *Wr2t = AP(__half, OFF_WR2T), *Wl3t = AP(__half, OFF_WL3T), *W3t = AP(__half, OFF_W3T);
    float  *bA   = AP(float, OFF_BA),    *bC   = AP(float, OFF_BC);
    int *cnt = AP(int, OFF_CNT), *rowstart = AP(int, OFF_ROWST);
    int *cursor = AP(int, OFF_CURSOR), *csr = AP(int, OFF_CSR);

    // [1] W1,W2 -> fp16 (one launch)
    {
        int n4 = F_IN * PROJ / 4;
        tohalf2_kernel<<<(2 * n4 + 255) / 256, 256>>>(
            (const float4*)W1, (__half2*)W1H, (const float4*)W2, (__half2*)W2H, n4);
    }
    // [2] all transposes + bias folds + bC zero (one launch)
    prep_kernel<<<TBLOCKS + 3, 256>>>(Wl1, Wl2, Wr1, Wr2, Wl3, W3, Wr3,
                                      Wl1t, Wl2t, Wr1t, Wr2t, Wl3t, W3t,
                                      WCt + (size_t)256 * F_IN,
                                      b1, b2, bA, bC);
    // [3] foldA: WAt[512,768] = [Wl1t;Wl2t][512,1024] @ W1H^T  (= [(W1Wl1)^T;(W1Wl2)^T])
    gemm_f16(512, F_IN, PROJ, Wl1t, W1H, WAt, F_IN, nullptr);
    // [4] foldC: WCt rows 0-255 = (W2@Wr1)^T
    gemm_f16(HID, F_IN, PROJ, Wr1t, W2H, WCt, F_IN, nullptr);
    // [5] activations -> fp16 (one launch)
    {
        int n4 = (int)(NR * F_IN / 4);
        tohalf2_kernel<<<(2 * n4 + 255) / 256, 256>>>(
            (const float4*)article_x, (__half2*)AxH,
            (const float4*)community_x, (__half2*)CxH, n4);
    }
    // [6] A12H = article_x @ [W1Wl1 | W1Wl2] + bA   (fp16: gather source)  <- ncu slot
    gemm_f16(NROWS, 512, F_IN, AxH, WAt, A12H, 512, bA);
    // [7] CC = community_x @ [W2Wr1 | Wr3] + bC     (fp32: streamed addend)
    gemm_f32(NROWS, 512, F_IN, CxH, WCt, CC, 512, bC);

    // [8-11] CSR build for all three graphs
    cudaMemsetAsync(cnt, 0, 3 * NROWS * sizeof(int));
    {
        int Etot = E0 + E1 + E2;
        count3_kernel<<<(Etot + 255) / 256, 256>>>(e_wb, E0, e_mb, E1, e_int, E2, cnt);
        scan3_kernel<<<3, 1024>>>(cnt, rowstart, cursor);
        fill3_kernel<<<(Etot + 255) / 256, 256>>>(e_wb, E0, e_mb, E1, e_int, E2, cursor, csr);
    }

    // [12] conv1: h1 = relu(mean(A1[src]) + bl1 + C1)
    aggregate_kernel<<<NROWS, 128>>>(rowstart, csr,
                                     (const __half2*)A12H, 256, CC, 512, bl1, (__half2*)h1H);
    // [13] h1r = h1 @ Wr2
    gemm_f32(NROWS, HID, HID, h1H, Wr2t, h1r, HID, nullptr);
    // [14] conv2: h2 = relu(mean(A2[src]) + bl2 + h1r)
    aggregate_kernel<<<NROWS, 128>>>(rowstart + (NROWS + 1), csr + E0,
                                     (const __half2*)(A12H + HID), 256, h1r, HID, bl2,
                                     (__half2*)h2H);
    // [15] t = h2 @ Wl3 (fp16: gather source)
    gemm_f16(NROWS, HID, HID, h2H, Wl3t, tH, HID, nullptr);
    // [16] conv3: h3 = relu(mean(t[src]) + bl3 + CC[:,256:512])
    aggregate_kernel<<<NROWS, 128>>>(rowstart + 2 * (NROWS + 1), csr + E0 + E1,
                                     (const __half2*)tH, 128, CC + HID, 512, bl3,
                                     (__half2*)h3H);
    // [17] out = h3 @ W3 + b3 (fp32 to d_out)
    gemm_f32(NROWS, OUTD, HID, h3H, W3t, (float*)d_out, OUTD, b3);
}